// round 15
// baseline (speedup 1.0000x reference)
#include <cuda_runtime.h>

// ScorePredictor: 3x DistMult edge scoring.
// score[e] = clip( sum_d head[src[e],d] * rel[d] * tail[dst[e],d], 0, 1 )
//
// R14 anchor (272.8us; score kernel at the LTS roofline ~96%) with TWO
// same-mechanism micro-tweaks in the atomic-latency-bound sort kernels:
//  - scatter ILP 4 -> 2 (more resident blocks x 2 chains = more outstanding
//    ATOMG; R14 showed warps x chains is the invariant that matters)
//  - hist 2 edges/thread (RED fire-and-forget; bound by key LDG latency)
// Established invariants (violations regressed 30-70%):
//  - single stream only; NO multi-stream fork/join in capture
//  - ONE fused score launch; score kernel body untouched
//  - EPW=8 at __launch_bounds__(256,3)

#define D_DIM 2048
#define WARPS_PER_BLOCK 8
#define THREADS_PER_BLOCK (WARPS_PER_BLOCK * 32)
#define EDGES_PER_WARP 8
#define EDGES_PER_BLOCK (WARPS_PER_BLOCK * EDGES_PER_WARP)

#define MAX_BINS 32768
#define MAX_E    131072

__device__ int  g_hist[3][MAX_BINS];
__device__ int4 g_edge[3][MAX_E];    // (key, other, edge, pad)

// ---------------- sort: zero / hist / scan / scatter ----------------

// Zero only the bins each phase actually uses: [0]=n0, [1]=n12, [2]=n12.
__global__ void zero_hist_kernel(int n0, int n12) {
    int i = blockIdx.x * blockDim.x + threadIdx.x;
    if (i < n0)                 g_hist[0][i] = 0;
    else if (i < n0 + n12)      g_hist[1][i - n0] = 0;
    else if (i < n0 + 2 * n12)  g_hist[2][i - n0 - n12] = 0;
}

// 2 consecutive edges per thread: 2 independent key loads + REDs.
__global__ void hist_kernel(const int* __restrict__ k0,   // ddi_src
                            const int* __restrict__ k1,   // dpi_dst
                            const int* __restrict__ k2,   // ppi_src
                            int E) {
    const int q = (E + 1) >> 1;                 // thread-slots per phase
    int i = blockIdx.x * blockDim.x + threadIdx.x;
    if (i >= 3 * q) return;
    int p = i / q, r = i - p * q;
    const int* ks = (p == 0) ? k0 : (p == 1) ? k1 : k2;
    const int e0 = r * 2;
    #pragma unroll
    for (int j = 0; j < 2; ++j) {
        int e = e0 + j;
        if (e >= E) break;
        atomicAdd(&g_hist[p][__ldg(ks + e)], 1);
    }
}

__global__ void scan_kernel(int nbins0, int nbins12) {
    const int p = blockIdx.x;           // one block per phase
    const int nbins = (p == 0) ? nbins0 : nbins12;
    int* h = g_hist[p];
    const int T = 1024;
    const int t = threadIdx.x;
    __shared__ int buf[2][1024];

    int chunk = (nbins + T - 1) / T;
    int start = t * chunk;
    int end   = min(start + chunk, nbins);

    int s = 0;
    for (int i = start; i < end; ++i) s += h[i];
    buf[0][t] = s;
    __syncthreads();

    int src = 0;
    for (int off = 1; off < T; off <<= 1) {
        int v = buf[src][t];
        if (t >= off) v += buf[src][t - off];
        buf[src ^ 1][t] = v;
        src ^= 1;
        __syncthreads();
    }

    int base = (t == 0) ? 0 : buf[src][t - 1];
    int run = base;
    for (int i = start; i < end; ++i) {
        int v = h[i];
        h[i] = run;
        run += v;
    }
}

// 2 CONSECUTIVE edges per thread -> 2 independent ATOMG chains at ~2x the
// resident blocks of the ILP=4 variant (maximizes outstanding atomics).
__global__ void scatter_kernel(const int* __restrict__ s0, const int* __restrict__ d0,
                               const int* __restrict__ s1, const int* __restrict__ d1,
                               const int* __restrict__ s2, const int* __restrict__ d2,
                               int E) {
    const int q = (E + 1) >> 1;                 // thread-slots per phase
    int i = blockIdx.x * blockDim.x + threadIdx.x;
    if (i >= 3 * q) return;
    int p = i / q, r = i - p * q;

    const int* ks = (p == 0) ? s0 : (p == 1) ? d1 : s2;   // grouping key
    const int* os = (p == 0) ? d0 : (p == 1) ? s1 : d2;   // other endpoint

    const int e0 = r * 2;
    #pragma unroll
    for (int j = 0; j < 2; ++j) {
        int e = e0 + j;
        if (e >= E) break;
        int k = __ldg(ks + e);
        int o = __ldg(os + e);
        int pos = atomicAdd(&g_hist[p][k], 1);
        g_edge[p][pos] = make_int4(k, o, e, 0);
    }
}

// ---------------- fused score ----------------

__global__ __launch_bounds__(THREADS_PER_BLOCK, 3)
void edge_score_fused(
    const float* __restrict__ x_drug,
    const float* __restrict__ x_prot,
    const float* __restrict__ rel_ddi,
    const float* __restrict__ rel_dpi,
    float*       __restrict__ out,
    int E, int blocks_per_phase)
{
    const int phase = blockIdx.x / blocks_per_phase;
    const int blk   = blockIdx.x - phase * blocks_per_phase;

    // Table binding: sorted-side table (heads), random-side table (tails).
    const float* xs;  const float* xr;  const float* rel;  float* o;
    if (phase == 0)      { xs = x_drug; xr = x_drug; rel = rel_ddi; o = out; }
    else if (phase == 1) { xs = x_prot; xr = x_drug; rel = rel_dpi; o = out + E; }
    else                 { xs = x_prot; xr = x_prot; rel = rel_dpi; o = out + 2 * E; }
    const int4* recs = g_edge[phase];

    const int warp = threadIdx.x >> 5;
    const int lane = threadIdx.x & 31;
    const int base = (blk * WARPS_PER_BLOCK + warp) * EDGES_PER_WARP;
    if (base >= E) return;

    // Lanes 0..7 fetch packed edge records; broadcast via shuffles.
    int pos = base + lane;
    if (pos >= E) pos = E - 1;              // duplicate last edge (same output)
    int my_s = 0, my_d = 0, my_edge = 0;
    if (lane < EDGES_PER_WARP) {
        int4 r = __ldg(recs + pos);
        my_s = r.x; my_d = r.y; my_edge = r.z;
    }

    int s[EDGES_PER_WARP], dI[EDGES_PER_WARP];
    #pragma unroll
    for (int e = 0; e < EDGES_PER_WARP; ++e) {
        s[e]  = __shfl_sync(0xffffffffu, my_s, e);
        dI[e] = __shfl_sync(0xffffffffu, my_d, e);
    }

    float acc[EDGES_PER_WARP];
    #pragma unroll
    for (int e = 0; e < EDGES_PER_WARP; ++e) acc[e] = 0.0f;

    // 16 k-chunks of float4 per lane. Batch all 8 independent tail loads
    // before the FMA block so ptxas issues them back-to-back (MLP=8).
    #pragma unroll 2
    for (int k = 0; k < D_DIM / (32 * 4); ++k) {
        const int idx = (k * 32 + lane) * 4;

        float4 t[EDGES_PER_WARP];
        #pragma unroll
        for (int e = 0; e < EDGES_PER_WARP; ++e)
            t[e] = __ldg(reinterpret_cast<const float4*>(
                       xr + (size_t)dI[e] * D_DIM + idx));

        const float4 r = __ldg(reinterpret_cast<const float4*>(rel + idx));

        float4 hr;   // head chunk pre-multiplied by rel; reload on key change
        #pragma unroll
        for (int e = 0; e < EDGES_PER_WARP; ++e) {
            if (e == 0 || s[e] != s[e - 1]) {   // warp-uniform branch
                float4 h = __ldg(reinterpret_cast<const float4*>(
                               xs + (size_t)s[e] * D_DIM + idx));
                hr.x = h.x * r.x; hr.y = h.y * r.y;
                hr.z = h.z * r.z; hr.w = h.w * r.w;
            }
            acc[e] = fmaf(hr.x, t[e].x, acc[e]);
            acc[e] = fmaf(hr.y, t[e].y, acc[e]);
            acc[e] = fmaf(hr.z, t[e].z, acc[e]);
            acc[e] = fmaf(hr.w, t[e].w, acc[e]);
        }
    }

    // Reduce and write each edge's score.
    #pragma unroll
    for (int e = 0; e < EDGES_PER_WARP; ++e) {
        float a = acc[e];
        #pragma unroll
        for (int off = 16; off > 0; off >>= 1)
            a += __shfl_xor_sync(0xffffffffu, a, off);
        const int edge_e = __shfl_sync(0xffffffffu, my_edge, e);
        if (lane == 0)
            o[edge_e] = fminf(fmaxf(a, 0.0f), 1.0f);
    }
}

// ---------------- launch ----------------

extern "C" void kernel_launch(void* const* d_in, const int* in_sizes, int n_in,
                              void* d_out, int out_size)
{
    const float* x_drug  = (const float*)d_in[0];
    const float* x_prot  = (const float*)d_in[1];
    const float* rel_ddi = (const float*)d_in[2];
    const float* rel_dpi = (const float*)d_in[3];
    const int*   ddi_src = (const int*)d_in[4];
    const int*   ddi_dst = (const int*)d_in[5];
    const int*   dpi_src = (const int*)d_in[6];
    const int*   dpi_dst = (const int*)d_in[7];
    const int*   ppi_src = (const int*)d_in[8];
    const int*   ppi_dst = (const int*)d_in[9];
    float* out = (float*)d_out;

    const int E      = in_sizes[4];
    const int N_DRUG = in_sizes[0] / D_DIM;
    const int N_PROT = in_sizes[1] / D_DIM;

    const int nz = N_DRUG + 2 * N_PROT;
    zero_hist_kernel<<<(nz + 255) / 256, 256>>>(N_DRUG, N_PROT);

    const int q = (E + 1) / 2;
    hist_kernel<<<(3 * q + 255) / 256, 256>>>(ddi_src, dpi_dst, ppi_src, E);
    scan_kernel<<<3, 1024>>>(N_DRUG, N_PROT);
    scatter_kernel<<<(3 * q + 255) / 256, 256>>>(
        ddi_src, ddi_dst, dpi_src, dpi_dst, ppi_src, ppi_dst, E);

    const int bpp = (E + EDGES_PER_BLOCK - 1) / EDGES_PER_BLOCK;

    edge_score_fused<<<3 * bpp, THREADS_PER_BLOCK>>>(
        x_drug, x_prot, rel_ddi, rel_dpi, out, E, bpp);
}

// round 16
// speedup vs baseline: 1.0136x; 1.0136x over previous
#include <cuda_runtime.h>

// ScorePredictor: 3x DistMult edge scoring — FINAL (R14 configuration, 272.8us).
// score[e] = clip( sum_d head[src[e],d] * rel[d] * tail[dst[e],d], 0, 1 )
//
// Converged design, established over 15 rounds:
//  - Counting sort of each edge list by one endpoint (ddi:src, dpi:dst,
//    ppi:src) -> packed int4 records; gives sorted-side row reuse in L1/L2.
//  - ONE fused score launch; phases sequential in blockIdx order, preserving
//    L2 phase separation (ddi: 80MB drug table; dpi/ppi: protein table).
//  - Score kernel at ~96% of the path-independent LTS cap (~2.7GB @ ~11.3TB/s).
// Falsified alternatives (do NOT revisit): multi-stream fork/join in capture
// (422/462us), split score launches (467us), EPW=16 (spills, 367us),
// volatile-asm loads (serialize, 539us), rel-in-registers (occupancy, 539us),
// scatter ILP/occupancy tuning (pinned ~9us by L2-atomic serialization),
// fp16 tail compression (fails 1e-3 rel-err).

#define D_DIM 2048
#define WARPS_PER_BLOCK 8
#define THREADS_PER_BLOCK (WARPS_PER_BLOCK * 32)
#define EDGES_PER_WARP 8
#define EDGES_PER_BLOCK (WARPS_PER_BLOCK * EDGES_PER_WARP)

#define MAX_BINS 32768
#define MAX_E    131072

__device__ int  g_hist[3][MAX_BINS];
__device__ int4 g_edge[3][MAX_E];    // (key, other, edge, pad)

// ---------------- sort: zero / hist / scan / scatter ----------------

// Zero only the bins each phase actually uses: [0]=n0, [1]=n12, [2]=n12.
__global__ void zero_hist_kernel(int n0, int n12) {
    int i = blockIdx.x * blockDim.x + threadIdx.x;
    if (i < n0)                 g_hist[0][i] = 0;
    else if (i < n0 + n12)      g_hist[1][i - n0] = 0;
    else if (i < n0 + 2 * n12)  g_hist[2][i - n0 - n12] = 0;
}

__global__ void hist_kernel(const int* __restrict__ k0,   // ddi_src
                            const int* __restrict__ k1,   // dpi_dst
                            const int* __restrict__ k2,   // ppi_src
                            int E) {
    int i = blockIdx.x * blockDim.x + threadIdx.x;
    if (i >= 3 * E) return;
    int p = i / E, e = i - p * E;
    int key = (p == 0) ? __ldg(k0 + e) : (p == 1) ? __ldg(k1 + e) : __ldg(k2 + e);
    atomicAdd(&g_hist[p][key], 1);
}

__global__ void scan_kernel(int nbins0, int nbins12) {
    const int p = blockIdx.x;           // one block per phase
    const int nbins = (p == 0) ? nbins0 : nbins12;
    int* h = g_hist[p];
    const int T = 1024;
    const int t = threadIdx.x;
    __shared__ int buf[2][1024];

    int chunk = (nbins + T - 1) / T;
    int start = t * chunk;
    int end   = min(start + chunk, nbins);

    int s = 0;
    for (int i = start; i < end; ++i) s += h[i];
    buf[0][t] = s;
    __syncthreads();

    int src = 0;
    for (int off = 1; off < T; off <<= 1) {
        int v = buf[src][t];
        if (t >= off) v += buf[src][t - off];
        buf[src ^ 1][t] = v;
        src ^= 1;
        __syncthreads();
    }

    int base = (t == 0) ? 0 : buf[src][t - 1];
    int run = base;
    for (int i = start; i < end; ++i) {
        int v = h[i];
        h[i] = run;
        run += v;
    }
}

// 4 consecutive edges per thread -> 4 independent ATOMG chains.
__global__ void scatter_kernel(const int* __restrict__ s0, const int* __restrict__ d0,
                               const int* __restrict__ s1, const int* __restrict__ d1,
                               const int* __restrict__ s2, const int* __restrict__ d2,
                               int E) {
    const int q = (E + 3) >> 2;                 // thread-slots per phase
    int i = blockIdx.x * blockDim.x + threadIdx.x;
    if (i >= 3 * q) return;
    int p = i / q, r = i - p * q;

    const int* ks = (p == 0) ? s0 : (p == 1) ? d1 : s2;   // grouping key
    const int* os = (p == 0) ? d0 : (p == 1) ? s1 : d2;   // other endpoint

    const int e0 = r * 4;
    #pragma unroll
    for (int j = 0; j < 4; ++j) {
        int e = e0 + j;
        if (e >= E) break;
        int k = __ldg(ks + e);
        int o = __ldg(os + e);
        int pos = atomicAdd(&g_hist[p][k], 1);
        g_edge[p][pos] = make_int4(k, o, e, 0);
    }
}

// ---------------- fused score ----------------

__global__ __launch_bounds__(THREADS_PER_BLOCK, 3)
void edge_score_fused(
    const float* __restrict__ x_drug,
    const float* __restrict__ x_prot,
    const float* __restrict__ rel_ddi,
    const float* __restrict__ rel_dpi,
    float*       __restrict__ out,
    int E, int blocks_per_phase)
{
    const int phase = blockIdx.x / blocks_per_phase;
    const int blk   = blockIdx.x - phase * blocks_per_phase;

    // Table binding: sorted-side table (heads), random-side table (tails).
    const float* xs;  const float* xr;  const float* rel;  float* o;
    if (phase == 0)      { xs = x_drug; xr = x_drug; rel = rel_ddi; o = out; }
    else if (phase == 1) { xs = x_prot; xr = x_drug; rel = rel_dpi; o = out + E; }
    else                 { xs = x_prot; xr = x_prot; rel = rel_dpi; o = out + 2 * E; }
    const int4* recs = g_edge[phase];

    const int warp = threadIdx.x >> 5;
    const int lane = threadIdx.x & 31;
    const int base = (blk * WARPS_PER_BLOCK + warp) * EDGES_PER_WARP;
    if (base >= E) return;

    // Lanes 0..7 fetch packed edge records; broadcast via shuffles.
    int pos = base + lane;
    if (pos >= E) pos = E - 1;              // duplicate last edge (same output)
    int my_s = 0, my_d = 0, my_edge = 0;
    if (lane < EDGES_PER_WARP) {
        int4 r = __ldg(recs + pos);
        my_s = r.x; my_d = r.y; my_edge = r.z;
    }

    int s[EDGES_PER_WARP], dI[EDGES_PER_WARP];
    #pragma unroll
    for (int e = 0; e < EDGES_PER_WARP; ++e) {
        s[e]  = __shfl_sync(0xffffffffu, my_s, e);
        dI[e] = __shfl_sync(0xffffffffu, my_d, e);
    }

    float acc[EDGES_PER_WARP];
    #pragma unroll
    for (int e = 0; e < EDGES_PER_WARP; ++e) acc[e] = 0.0f;

    // 16 k-chunks of float4 per lane. Batch all 8 independent tail loads
    // before the FMA block so ptxas issues them back-to-back (MLP=8).
    #pragma unroll 2
    for (int k = 0; k < D_DIM / (32 * 4); ++k) {
        const int idx = (k * 32 + lane) * 4;

        float4 t[EDGES_PER_WARP];
        #pragma unroll
        for (int e = 0; e < EDGES_PER_WARP; ++e)
            t[e] = __ldg(reinterpret_cast<const float4*>(
                       xr + (size_t)dI[e] * D_DIM + idx));

        const float4 r = __ldg(reinterpret_cast<const float4*>(rel + idx));

        float4 hr;   // head chunk pre-multiplied by rel; reload on key change
        #pragma unroll
        for (int e = 0; e < EDGES_PER_WARP; ++e) {
            if (e == 0 || s[e] != s[e - 1]) {   // warp-uniform branch
                float4 h = __ldg(reinterpret_cast<const float4*>(
                               xs + (size_t)s[e] * D_DIM + idx));
                hr.x = h.x * r.x; hr.y = h.y * r.y;
                hr.z = h.z * r.z; hr.w = h.w * r.w;
            }
            acc[e] = fmaf(hr.x, t[e].x, acc[e]);
            acc[e] = fmaf(hr.y, t[e].y, acc[e]);
            acc[e] = fmaf(hr.z, t[e].z, acc[e]);
            acc[e] = fmaf(hr.w, t[e].w, acc[e]);
        }
    }

    // Reduce and write each edge's score.
    #pragma unroll
    for (int e = 0; e < EDGES_PER_WARP; ++e) {
        float a = acc[e];
        #pragma unroll
        for (int off = 16; off > 0; off >>= 1)
            a += __shfl_xor_sync(0xffffffffu, a, off);
        const int edge_e = __shfl_sync(0xffffffffu, my_edge, e);
        if (lane == 0)
            o[edge_e] = fminf(fmaxf(a, 0.0f), 1.0f);
    }
}

// ---------------- launch ----------------

extern "C" void kernel_launch(void* const* d_in, const int* in_sizes, int n_in,
                              void* d_out, int out_size)
{
    const float* x_drug  = (const float*)d_in[0];
    const float* x_prot  = (const float*)d_in[1];
    const float* rel_ddi = (const float*)d_in[2];
    const float* rel_dpi = (const float*)d_in[3];
    const int*   ddi_src = (const int*)d_in[4];
    const int*   ddi_dst = (const int*)d_in[5];
    const int*   dpi_src = (const int*)d_in[6];
    const int*   dpi_dst = (const int*)d_in[7];
    const int*   ppi_src = (const int*)d_in[8];
    const int*   ppi_dst = (const int*)d_in[9];
    float* out = (float*)d_out;

    const int E      = in_sizes[4];
    const int N_DRUG = in_sizes[0] / D_DIM;
    const int N_PROT = in_sizes[1] / D_DIM;

    const int nz = N_DRUG + 2 * N_PROT;
    zero_hist_kernel<<<(nz + 255) / 256, 256>>>(N_DRUG, N_PROT);
    hist_kernel<<<(3 * E + 255) / 256, 256>>>(ddi_src, dpi_dst, ppi_src, E);
    scan_kernel<<<3, 1024>>>(N_DRUG, N_PROT);

    const int q = (E + 3) / 4;
    scatter_kernel<<<(3 * q + 255) / 256, 256>>>(
        ddi_src, ddi_dst, dpi_src, dpi_dst, ppi_src, ppi_dst, E);

    const int bpp = (E + EDGES_PER_BLOCK - 1) / EDGES_PER_BLOCK;

    edge_score_fused<<<3 * bpp, THREADS_PER_BLOCK>>>(
        x_drug, x_prot, rel_ddi, rel_dpi, out, E, bpp);
}

// round 17
// speedup vs baseline: 1.0278x; 1.0140x over previous
#include <cuda_runtime.h>

// ScorePredictor: 3x DistMult edge scoring (best: 272.8us, R14 config).
// score[e] = clip( sum_d head[src[e],d] * rel[d] * tail[dst[e],d], 0, 1 )
//
// R17 delta (ONE change): the zero_hist launch is deleted; the fused score
// kernel zeros the histogram bins as trivial prefix work (~11 bins/block,
// no early return). Score never reads g_hist, bins are zero at module load,
// and every call leaves them zeroed for the next call's hist -> the zero
// invariant holds on every execution (correctness run + each graph replay).
//
// Converged invariants (violations regressed 30-70% — do NOT revisit):
//  - single stream only; NO multi-stream fork/join in capture (422/462us)
//  - ONE fused score launch (split scores: 310..467us)
//  - EPW=8 at __launch_bounds__(256,3) (EPW=16 spills: 367us)
//  - plain __ldg loads, batched tails (volatile asm serializes: 539us)
//  - hist/scatter atomic tuning is a no-op (pinned ~9us at occ 23/41/74%)
//  - fp16/bf16 tail compression fails the 1e-3 rel-err budget

#define D_DIM 2048
#define WARPS_PER_BLOCK 8
#define THREADS_PER_BLOCK (WARPS_PER_BLOCK * 32)
#define EDGES_PER_WARP 8
#define EDGES_PER_BLOCK (WARPS_PER_BLOCK * EDGES_PER_WARP)

#define MAX_BINS 32768
#define MAX_E    131072

__device__ int  g_hist[3][MAX_BINS];   // zero at module load; re-zeroed by score
__device__ int4 g_edge[3][MAX_E];      // (key, other, edge, pad)

// ---------------- sort: hist / scan / scatter ----------------

__global__ void hist_kernel(const int* __restrict__ k0,   // ddi_src
                            const int* __restrict__ k1,   // dpi_dst
                            const int* __restrict__ k2,   // ppi_src
                            int E) {
    int i = blockIdx.x * blockDim.x + threadIdx.x;
    if (i >= 3 * E) return;
    int p = i / E, e = i - p * E;
    int key = (p == 0) ? __ldg(k0 + e) : (p == 1) ? __ldg(k1 + e) : __ldg(k2 + e);
    atomicAdd(&g_hist[p][key], 1);
}

__global__ void scan_kernel(int nbins0, int nbins12) {
    const int p = blockIdx.x;           // one block per phase
    const int nbins = (p == 0) ? nbins0 : nbins12;
    int* h = g_hist[p];
    const int T = 1024;
    const int t = threadIdx.x;
    __shared__ int buf[2][1024];

    int chunk = (nbins + T - 1) / T;
    int start = t * chunk;
    int end   = min(start + chunk, nbins);

    int s = 0;
    for (int i = start; i < end; ++i) s += h[i];
    buf[0][t] = s;
    __syncthreads();

    int src = 0;
    for (int off = 1; off < T; off <<= 1) {
        int v = buf[src][t];
        if (t >= off) v += buf[src][t - off];
        buf[src ^ 1][t] = v;
        src ^= 1;
        __syncthreads();
    }

    int base = (t == 0) ? 0 : buf[src][t - 1];
    int run = base;
    for (int i = start; i < end; ++i) {
        int v = h[i];
        h[i] = run;
        run += v;
    }
}

// 4 consecutive edges per thread -> 4 independent ATOMG chains.
__global__ void scatter_kernel(const int* __restrict__ s0, const int* __restrict__ d0,
                               const int* __restrict__ s1, const int* __restrict__ d1,
                               const int* __restrict__ s2, const int* __restrict__ d2,
                               int E) {
    const int q = (E + 3) >> 2;                 // thread-slots per phase
    int i = blockIdx.x * blockDim.x + threadIdx.x;
    if (i >= 3 * q) return;
    int p = i / q, r = i - p * q;

    const int* ks = (p == 0) ? s0 : (p == 1) ? d1 : s2;   // grouping key
    const int* os = (p == 0) ? d0 : (p == 1) ? s1 : d2;   // other endpoint

    const int e0 = r * 4;
    #pragma unroll
    for (int j = 0; j < 4; ++j) {
        int e = e0 + j;
        if (e >= E) break;
        int k = __ldg(ks + e);
        int o = __ldg(os + e);
        int pos = atomicAdd(&g_hist[p][k], 1);
        g_edge[p][pos] = make_int4(k, o, e, 0);
    }
}

// ---------------- fused score (+ histogram re-zero prefix) ----------------

__global__ __launch_bounds__(THREADS_PER_BLOCK, 3)
void edge_score_fused(
    const float* __restrict__ x_drug,
    const float* __restrict__ x_prot,
    const float* __restrict__ rel_ddi,
    const float* __restrict__ rel_dpi,
    float*       __restrict__ out,
    int E, int blocks_per_phase,
    int n0, int n12, int zpb)           // bins per phase, zero-slots per block
{
    // Prefix work: zero this block's slice of the histogram bins (score never
    // reads g_hist; this restores the zero invariant for the NEXT call).
    if (threadIdx.x < (unsigned)zpb) {
        int i = blockIdx.x * zpb + threadIdx.x;
        if (i < n0)                 g_hist[0][i] = 0;
        else if (i < n0 + n12)      g_hist[1][i - n0] = 0;
        else if (i < n0 + 2 * n12)  g_hist[2][i - n0 - n12] = 0;
    }

    const int phase = blockIdx.x / blocks_per_phase;
    const int blk   = blockIdx.x - phase * blocks_per_phase;

    // Table binding: sorted-side table (heads), random-side table (tails).
    const float* xs;  const float* xr;  const float* rel;  float* o;
    if (phase == 0)      { xs = x_drug; xr = x_drug; rel = rel_ddi; o = out; }
    else if (phase == 1) { xs = x_prot; xr = x_drug; rel = rel_dpi; o = out + E; }
    else                 { xs = x_prot; xr = x_prot; rel = rel_dpi; o = out + 2 * E; }
    const int4* recs = g_edge[phase];

    const int warp = threadIdx.x >> 5;
    const int lane = threadIdx.x & 31;
    const int base = (blk * WARPS_PER_BLOCK + warp) * EDGES_PER_WARP;
    if (base >= E) return;

    // Lanes 0..7 fetch packed edge records; broadcast via shuffles.
    int pos = base + lane;
    if (pos >= E) pos = E - 1;              // duplicate last edge (same output)
    int my_s = 0, my_d = 0, my_edge = 0;
    if (lane < EDGES_PER_WARP) {
        int4 r = __ldg(recs + pos);
        my_s = r.x; my_d = r.y; my_edge = r.z;
    }

    int s[EDGES_PER_WARP], dI[EDGES_PER_WARP];
    #pragma unroll
    for (int e = 0; e < EDGES_PER_WARP; ++e) {
        s[e]  = __shfl_sync(0xffffffffu, my_s, e);
        dI[e] = __shfl_sync(0xffffffffu, my_d, e);
    }

    float acc[EDGES_PER_WARP];
    #pragma unroll
    for (int e = 0; e < EDGES_PER_WARP; ++e) acc[e] = 0.0f;

    // 16 k-chunks of float4 per lane. Batch all 8 independent tail loads
    // before the FMA block so ptxas issues them back-to-back (MLP=8).
    #pragma unroll 2
    for (int k = 0; k < D_DIM / (32 * 4); ++k) {
        const int idx = (k * 32 + lane) * 4;

        float4 t[EDGES_PER_WARP];
        #pragma unroll
        for (int e = 0; e < EDGES_PER_WARP; ++e)
            t[e] = __ldg(reinterpret_cast<const float4*>(
                       xr + (size_t)dI[e] * D_DIM + idx));

        const float4 r = __ldg(reinterpret_cast<const float4*>(rel + idx));

        float4 hr;   // head chunk pre-multiplied by rel; reload on key change
        #pragma unroll
        for (int e = 0; e < EDGES_PER_WARP; ++e) {
            if (e == 0 || s[e] != s[e - 1]) {   // warp-uniform branch
                float4 h = __ldg(reinterpret_cast<const float4*>(
                               xs + (size_t)s[e] * D_DIM + idx));
                hr.x = h.x * r.x; hr.y = h.y * r.y;
                hr.z = h.z * r.z; hr.w = h.w * r.w;
            }
            acc[e] = fmaf(hr.x, t[e].x, acc[e]);
            acc[e] = fmaf(hr.y, t[e].y, acc[e]);
            acc[e] = fmaf(hr.z, t[e].z, acc[e]);
            acc[e] = fmaf(hr.w, t[e].w, acc[e]);
        }
    }

    // Reduce and write each edge's score.
    #pragma unroll
    for (int e = 0; e < EDGES_PER_WARP; ++e) {
        float a = acc[e];
        #pragma unroll
        for (int off = 16; off > 0; off >>= 1)
            a += __shfl_xor_sync(0xffffffffu, a, off);
        const int edge_e = __shfl_sync(0xffffffffu, my_edge, e);
        if (lane == 0)
            o[edge_e] = fminf(fmaxf(a, 0.0f), 1.0f);
    }
}

// ---------------- launch ----------------

extern "C" void kernel_launch(void* const* d_in, const int* in_sizes, int n_in,
                              void* d_out, int out_size)
{
    const float* x_drug  = (const float*)d_in[0];
    const float* x_prot  = (const float*)d_in[1];
    const float* rel_ddi = (const float*)d_in[2];
    const float* rel_dpi = (const float*)d_in[3];
    const int*   ddi_src = (const int*)d_in[4];
    const int*   ddi_dst = (const int*)d_in[5];
    const int*   dpi_src = (const int*)d_in[6];
    const int*   dpi_dst = (const int*)d_in[7];
    const int*   ppi_src = (const int*)d_in[8];
    const int*   ppi_dst = (const int*)d_in[9];
    float* out = (float*)d_out;

    const int E      = in_sizes[4];
    const int N_DRUG = in_sizes[0] / D_DIM;
    const int N_PROT = in_sizes[1] / D_DIM;

    // Bins are zero at entry (module load / previous call's score prefix).
    hist_kernel<<<(3 * E + 255) / 256, 256>>>(ddi_src, dpi_dst, ppi_src, E);
    scan_kernel<<<3, 1024>>>(N_DRUG, N_PROT);

    const int q = (E + 3) / 4;
    scatter_kernel<<<(3 * q + 255) / 256, 256>>>(
        ddi_src, ddi_dst, dpi_src, dpi_dst, ppi_src, ppi_dst, E);

    const int bpp    = (E + EDGES_PER_BLOCK - 1) / EDGES_PER_BLOCK;
    const int blocks = 3 * bpp;
    const int nz     = N_DRUG + 2 * N_PROT;
    const int zpb    = (nz + blocks - 1) / blocks;   // ~11 bins per block

    edge_score_fused<<<blocks, THREADS_PER_BLOCK>>>(
        x_drug, x_prot, rel_ddi, rel_dpi, out, E, bpp,
        N_DRUG, N_PROT, zpb);
}